// round 1
// baseline (speedup 1.0000x reference)
#include <cuda_runtime.h>
#include <cstdint>
#include <cstddef>

// Problem constants
#define BB 8
#define CC_TOT 128
#define HH 128
#define WW 128
#define RR 4          // search range
#define NOFF 81       // (2R+1)^2

// Tiling
#define TH 8          // tile height (pixels)
#define TW 32         // tile width (pixels)
#define PX 8          // pixels per thread along w
#define NGROUP 9      // dy groups (one warp each)
#define NT (NGROUP * 32)   // 288 threads
#define CCH 4         // channels per pipeline chunk

// Shared strides (padded for bank-conflict-free LDS.128)
#define FSTR 36       // first tile row stride (floats), 8 rows
#define SSTR 44       // second tile row stride (floats), 16 rows
#define SROWS (TH + 2*RR)   // 16
#define SCOLS (TW + 2*RR)   // 40 (stored), stride 44

__device__ __forceinline__ unsigned long long pk2(float lo, float hi) {
    unsigned long long r;
    asm("mov.b64 %0, {%1, %2};" : "=l"(r) : "f"(lo), "f"(hi));
    return r;
}

__device__ __forceinline__ void fma2(unsigned long long& d,
                                     unsigned long long a,
                                     unsigned long long b) {
    // packed f32x2 FMA: d.lo += a.lo*b.lo ; d.hi += a.hi*b.hi
    asm("fma.rn.f32x2 %0, %1, %2, %0;" : "+l"(d) : "l"(a), "l"(b));
}

__device__ __forceinline__ float2 upk2(unsigned long long v) {
    float2 r;
    asm("mov.b64 {%0, %1}, %2;" : "=f"(r.x), "=f"(r.y) : "l"(v));
    return r;
}

__device__ __forceinline__ void cpa16(float* dst, const float* src) {
    unsigned s = (unsigned)__cvta_generic_to_shared(dst);
    asm volatile("cp.async.ca.shared.global [%0], [%1], 16;" :: "r"(s), "l"(src));
}

__global__ void __launch_bounds__(NT, 1)
costvol_kernel(const float* __restrict__ first,
               const float* __restrict__ second,
               float* __restrict__ out) {
    __shared__ __align__(16) float sF[2][CCH][TH][FSTR];
    __shared__ __align__(16) float sS[2][CCH][SROWS][SSTR];

    const int tid = threadIdx.x;
    const int g   = tid >> 5;          // dy group 0..8 (dy = g-4)
    const int lid = tid & 31;
    const int lh  = lid >> 2;          // local row 0..7
    const int lwi = lid & 3;           // 0..3
    const int lw  = lwi << 3;          // local col base 0..24 step 8

    const int w0 = blockIdx.x * TW;
    const int h0 = blockIdx.y * TH;
    const int bz = blockIdx.z;

    const size_t batch_off = (size_t)bz * CC_TOT * HH * WW;
    const float* firstB  = first  + batch_off;
    const float* secondB = second + batch_off;

    // 36 packed accumulators: acc[d*4+q] holds pixels (q, q+4) for dx index d
    unsigned long long acc[36];
#pragma unroll
    for (int i = 0; i < 36; i++) acc[i] = 0ULL;

    // ------- pipelined chunk loader -------
    auto load_chunk = [&](int c0, int buf) {
        // second tile: CCH channels x 16 rows x 10 float4 slots
#pragma unroll 1
        for (int i = tid; i < CCH * SROWS * 10; i += NT) {
            int ch  = i / (SROWS * 10);
            int rem = i - ch * (SROWS * 10);
            int r   = rem / 10;
            int j   = rem - r * 10;
            int gh  = h0 - RR + r;
            int gw  = w0 - RR + 4 * j;
            float* dst = &sS[buf][ch][r][4 * j];
            if ((unsigned)gh < (unsigned)HH && (unsigned)gw < (unsigned)WW) {
                cpa16(dst, secondB + ((size_t)(c0 + ch) * HH + gh) * WW + gw);
            } else {
                *(float4*)dst = make_float4(0.f, 0.f, 0.f, 0.f);
            }
        }
        // first tile: CCH channels x 8 rows x 8 float4 slots (always in range)
#pragma unroll 1
        for (int i = tid; i < CCH * TH * 8; i += NT) {
            int ch  = i >> 6;
            int rem = i & 63;
            int r   = rem >> 3;
            int j   = rem & 7;
            cpa16(&sF[buf][ch][r][4 * j],
                  firstB + ((size_t)(c0 + ch) * HH + (h0 + r)) * WW + (w0 + 4 * j));
        }
        asm volatile("cp.async.commit_group;" ::: "memory");
    };

    load_chunk(0, 0);

    const int NCHUNK = CC_TOT / CCH;
#pragma unroll 1
    for (int cc = 0; cc < NCHUNK; cc++) {
        if (cc + 1 < NCHUNK) {
            load_chunk((cc + 1) * CCH, (cc + 1) & 1);
        } else {
            asm volatile("cp.async.commit_group;" ::: "memory");
        }
        asm volatile("cp.async.wait_group 1;" ::: "memory");
        __syncthreads();

        const int buf = cc & 1;
#pragma unroll
        for (int ch = 0; ch < CCH; ch++) {
            // first values for this thread's 8 pixels
            const float* Fp = &sF[buf][ch][lh][lw];
            float4 fa = *(const float4*)Fp;
            float4 fb = *(const float4*)(Fp + 4);
            unsigned long long pa0 = pk2(fa.x, fb.x);
            unsigned long long pa1 = pk2(fa.y, fb.y);
            unsigned long long pa2 = pk2(fa.z, fb.z);
            unsigned long long pa3 = pk2(fa.w, fb.w);

            // second window: 16 contiguous floats at row lh+g
            const float* Sp = &sS[buf][ch][lh + g][lw];
            float4 s0 = *(const float4*)Sp;
            float4 s1 = *(const float4*)(Sp + 4);
            float4 s2 = *(const float4*)(Sp + 8);
            float4 s3 = *(const float4*)(Sp + 12);
            float wv[16] = { s0.x, s0.y, s0.z, s0.w,
                             s1.x, s1.y, s1.z, s1.w,
                             s2.x, s2.y, s2.z, s2.w,
                             s3.x, s3.y, s3.z, s3.w };
            unsigned long long pw[12];
#pragma unroll
            for (int k = 0; k < 12; k++) pw[k] = pk2(wv[k], wv[k + 4]);

#pragma unroll
            for (int d = 0; d < 9; d++) {
                fma2(acc[d * 4 + 0], pa0, pw[d + 0]);
                fma2(acc[d * 4 + 1], pa1, pw[d + 1]);
                fma2(acc[d * 4 + 2], pa2, pw[d + 2]);
                fma2(acc[d * 4 + 3], pa3, pw[d + 3]);
            }
        }
        __syncthreads();
    }

    // ------- store: mean over C, out[b, g*9+d, h, w] -------
    const float inv = 1.0f / (float)CC_TOT;
#pragma unroll
    for (int d = 0; d < 9; d++) {
        float2 v0 = upk2(acc[d * 4 + 0]);
        float2 v1 = upk2(acc[d * 4 + 1]);
        float2 v2 = upk2(acc[d * 4 + 2]);
        float2 v3 = upk2(acc[d * 4 + 3]);
        float4 lo = make_float4(v0.x * inv, v1.x * inv, v2.x * inv, v3.x * inv);
        float4 hi = make_float4(v0.y * inv, v1.y * inv, v2.y * inv, v3.y * inv);
        int o = g * 9 + d;
        float* op = out + (((size_t)bz * NOFF + o) * HH + (h0 + lh)) * WW + (w0 + lw);
        *(float4*)op       = lo;
        *(float4*)(op + 4) = hi;
    }
}

extern "C" void kernel_launch(void* const* d_in, const int* in_sizes, int n_in,
                              void* d_out, int out_size) {
    const float* first  = (const float*)d_in[0];
    const float* second = (const float*)d_in[1];
    float* out = (float*)d_out;

    dim3 grid(WW / TW, HH / TH, BB);   // (4, 16, 8) = 512 blocks
    costvol_kernel<<<grid, NT>>>(first, second, out);
}

// round 2
// speedup vs baseline: 1.7699x; 1.7699x over previous
#include <cuda_runtime.h>
#include <cstdint>
#include <cstddef>

// Problem constants
#define BB 8
#define CCT 128
#define HH 128
#define WW 128
#define RR 4
#define NOFF 81

// Tiling
#define TH 8
#define TW 32
#define NGROUP 9
#define NT (NGROUP * 32)      // 288 threads
#define CCH 8                 // channels per chunk
#define NCHUNK (CCT / CCH)    // 16

// Shared layout (floats)
#define FSTR 36
#define SSTR 44
#define SROWS 16
#define F_CH_FLOATS (TH * FSTR)           // 288
#define S_CH_FLOATS (SROWS * SSTR)        // 704
#define F_BUF_FLOATS (CCH * F_CH_FLOATS)  // 2304
#define S_BUF_FLOATS (CCH * S_CH_FLOATS)  // 5632
#define F_OFF 0
#define S_OFF (2 * F_BUF_FLOATS)          // 4608
#define SMEM_FLOATS (S_OFF + 2 * S_BUF_FLOATS)   // 15872
#define SMEM_BYTES (SMEM_FLOATS * 4)      // 63488

#define NS_SLOTS (CCH * SROWS * 10)       // 1280
#define NF_SLOTS (CCH * TH * 8)           // 512
#define KS 5
#define KF 2
#define CH_STRIDE ((size_t)CCH * HH * WW)

typedef unsigned long long u64;

__device__ __forceinline__ u64 pk2(float lo, float hi) {
    u64 r;
    asm("mov.b64 %0, {%1, %2};" : "=l"(r) : "f"(lo), "f"(hi));
    return r;
}
__device__ __forceinline__ float lo_f(u64 v) { return __uint_as_float((unsigned)v); }
__device__ __forceinline__ float hi_f(u64 v) { return __uint_as_float((unsigned)(v >> 32)); }

__device__ __forceinline__ void fma2(u64& d, u64 a, u64 b) {
    asm("fma.rn.f32x2 %0, %1, %2, %0;" : "+l"(d) : "l"(a), "l"(b));
}
__device__ __forceinline__ void cpa16(float* dst, const float* src) {
    unsigned s = (unsigned)__cvta_generic_to_shared(dst);
    asm volatile("cp.async.ca.shared.global [%0], [%1], 16;" :: "r"(s), "l"(src));
}

__global__ void __launch_bounds__(NT, 1)
costvol_kernel(const float* __restrict__ first,
               const float* __restrict__ second,
               float* __restrict__ out) {
    extern __shared__ __align__(16) float smem[];

    const int tid = threadIdx.x;
    const int g   = tid >> 5;          // dy index 0..8
    const int lid = tid & 31;
    const int lh  = lid >> 2;          // local row 0..7
    const int lw  = (lid & 3) << 3;    // local col base {0,8,16,24}

    const int w0 = blockIdx.x * TW;
    const int h0 = blockIdx.y * TH;
    const int bz = blockIdx.z;

    const size_t batch_off = (size_t)bz * CCT * HH * WW;
    const float* firstB  = first  + batch_off;
    const float* secondB = second + batch_off;

    // ---------- precompute loader slots ----------
    const float* s_src[KS];
    unsigned     s_dst[KS];
    bool         s_val[KS];
#pragma unroll
    for (int k = 0; k < KS; k++) {
        int s = tid + k * NT;
        bool v = (s < NS_SLOTS);
        int ss = v ? s : 0;
        int ch  = ss / 160;
        int rem = ss - ch * 160;
        int r   = rem / 10;
        int j   = rem - r * 10;
        int gh = h0 - RR + r;
        int gw = w0 - RR + 4 * j;
        v = v && ((unsigned)gh < (unsigned)HH) && ((unsigned)gw < (unsigned)WW);
        s_val[k] = v;
        s_src[k] = secondB + ((size_t)ch * HH + gh) * WW + gw;
        s_dst[k] = (unsigned)((ch * SROWS + r) * SSTR + 4 * j);
    }
    const float* f_src[KF];
    unsigned     f_dst[KF];
    bool         f_val[KF];
#pragma unroll
    for (int k = 0; k < KF; k++) {
        int s = tid + k * NT;
        bool v = (s < NF_SLOTS);
        int ss = v ? s : 0;
        int ch = ss >> 6;
        int r  = (ss >> 3) & 7;
        int j  = ss & 7;
        f_val[k] = v;
        f_src[k] = firstB + ((size_t)ch * HH + (h0 + r)) * WW + (w0 + 4 * j);
        f_dst[k] = (unsigned)((ch * TH + r) * FSTR + 4 * j);
    }

    // ---------- zero-prefill (handles halo padding once) ----------
    for (int i = tid * 4; i < SMEM_FLOATS; i += NT * 4)
        *(float4*)(smem + i) = make_float4(0.f, 0.f, 0.f, 0.f);
    __syncthreads();

    // ---------- chunk issuer ----------
    auto issue = [&](int buf) {
        float* sbase = smem + S_OFF + buf * S_BUF_FLOATS;
        float* fbase = smem + F_OFF + buf * F_BUF_FLOATS;
#pragma unroll
        for (int k = 0; k < KS; k++) {
            if (s_val[k]) cpa16(sbase + s_dst[k], s_src[k]);
            s_src[k] += CH_STRIDE;
        }
#pragma unroll
        for (int k = 0; k < KF; k++) {
            if (f_val[k]) cpa16(fbase + f_dst[k], f_src[k]);
            f_src[k] += CH_STRIDE;
        }
        asm volatile("cp.async.commit_group;" ::: "memory");
    };

    issue(0);

    // ---------- accumulators ----------
    u64 accE[5][4];           // even dx = 2e; pixel pairs (0,1)(2,3)(4,5)(6,7)
    u64 accO[4][3];           // odd dx = 2o+1; pixel pairs (1,2)(3,4)(5,6)
    float acc0[4], acc7[4];   // odd dx boundary pixels 0 and 7
#pragma unroll
    for (int e = 0; e < 5; e++)
#pragma unroll
        for (int p = 0; p < 4; p++) accE[e][p] = 0ULL;
#pragma unroll
    for (int o = 0; o < 4; o++) {
#pragma unroll
        for (int p = 0; p < 3; p++) accO[o][p] = 0ULL;
        acc0[o] = 0.f; acc7[o] = 0.f;
    }

    const float* Fb0 = smem + F_OFF + lh * FSTR + lw;
    const float* Fb1 = Fb0 + F_BUF_FLOATS;
    const float* Sb0 = smem + S_OFF + (lh + g) * SSTR + lw;
    const float* Sb1 = Sb0 + S_BUF_FLOATS;

#pragma unroll 1
    for (int cc = 0; cc < NCHUNK; cc++) {
        if (cc + 1 < NCHUNK) {
            issue((cc + 1) & 1);
            asm volatile("cp.async.wait_group 1;" ::: "memory");
        } else {
            asm volatile("cp.async.wait_group 0;" ::: "memory");
        }
        __syncthreads();

        const float* Fp = (cc & 1) ? Fb1 : Fb0;
        const float* Sp = (cc & 1) ? Sb1 : Sb0;

#pragma unroll
        for (int ch = 0; ch < CCH; ch++) {
            const float* fptr = Fp + ch * F_CH_FLOATS;
            const float* sptr = Sp + ch * S_CH_FLOATS;

            // first: 4 aligned pairs + scalar views
            ulonglong2 fA = *(const ulonglong2*)fptr;
            ulonglong2 fB = *(const ulonglong2*)(fptr + 4);
            u64 fp0 = fA.x, fp1 = fA.y, fp2 = fB.x, fp3 = fB.y;
            float f0 = lo_f(fp0), f1 = hi_f(fp0);
            float f2 = lo_f(fp1), f3 = hi_f(fp1);
            float f4 = lo_f(fp2), f5 = hi_f(fp2);
            float f6 = lo_f(fp3), f7 = hi_f(fp3);
            u64 op0 = pk2(f1, f2);
            u64 op1 = pk2(f3, f4);
            u64 op2 = pk2(f5, f6);

            // second window: 8 aligned pairs (16 floats)
            ulonglong2 wA = *(const ulonglong2*)sptr;
            ulonglong2 wB = *(const ulonglong2*)(sptr + 4);
            ulonglong2 wC = *(const ulonglong2*)(sptr + 8);
            ulonglong2 wD = *(const ulonglong2*)(sptr + 12);
            u64 wp[8] = { wA.x, wA.y, wB.x, wB.y, wC.x, wC.y, wD.x, wD.y };

            // even dx = 2e: all operands aligned, zero packs
#pragma unroll
            for (int e = 0; e < 5; e++) {
                fma2(accE[e][0], fp0, wp[0 + e]);
                fma2(accE[e][1], fp1, wp[1 + e]);
                fma2(accE[e][2], fp2, wp[2 + e]);
                fma2(accE[e][3], fp3, wp[3 + e]);
            }
            // odd dx = 2o+1: window pairs aligned; 3 first-packs reused
#pragma unroll
            for (int o = 0; o < 4; o++) {
                fma2(accO[o][0], op0, wp[o + 1]);
                fma2(accO[o][1], op1, wp[o + 2]);
                fma2(accO[o][2], op2, wp[o + 3]);
                acc0[o] = fmaf(f0, hi_f(wp[o]),     acc0[o]);   // w[2o+1]
                acc7[o] = fmaf(f7, lo_f(wp[o + 4]), acc7[o]);   // w[8+2o]
            }
        }
        __syncthreads();
    }

    // ---------- store: mean over C ----------
    const float inv = 1.0f / (float)CCT;
    const size_t row_base = ((size_t)bz * NOFF) * HH * WW
                          + (size_t)(h0 + lh) * WW + (w0 + lw);
#pragma unroll
    for (int e = 0; e < 5; e++) {
        int o = g * 9 + 2 * e;
        float* op = out + row_base + (size_t)o * HH * WW;
        float4 v0 = make_float4(lo_f(accE[e][0]) * inv, hi_f(accE[e][0]) * inv,
                                lo_f(accE[e][1]) * inv, hi_f(accE[e][1]) * inv);
        float4 v1 = make_float4(lo_f(accE[e][2]) * inv, hi_f(accE[e][2]) * inv,
                                lo_f(accE[e][3]) * inv, hi_f(accE[e][3]) * inv);
        *(float4*)op       = v0;
        *(float4*)(op + 4) = v1;
    }
#pragma unroll
    for (int o2 = 0; o2 < 4; o2++) {
        int o = g * 9 + 2 * o2 + 1;
        float* op = out + row_base + (size_t)o * HH * WW;
        float4 v0 = make_float4(acc0[o2] * inv,
                                lo_f(accO[o2][0]) * inv, hi_f(accO[o2][0]) * inv,
                                lo_f(accO[o2][1]) * inv);
        float4 v1 = make_float4(hi_f(accO[o2][1]) * inv,
                                lo_f(accO[o2][2]) * inv, hi_f(accO[o2][2]) * inv,
                                acc7[o2] * inv);
        *(float4*)op       = v0;
        *(float4*)(op + 4) = v1;
    }
}

extern "C" void kernel_launch(void* const* d_in, const int* in_sizes, int n_in,
                              void* d_out, int out_size) {
    const float* first  = (const float*)d_in[0];
    const float* second = (const float*)d_in[1];
    float* out = (float*)d_out;

    cudaFuncSetAttribute(costvol_kernel,
                         cudaFuncAttributeMaxDynamicSharedMemorySize, SMEM_BYTES);

    dim3 grid(WW / TW, HH / TH, BB);   // (4,16,8) = 512 blocks
    costvol_kernel<<<grid, NT, SMEM_BYTES>>>(first, second, out);
}